// round 12
// baseline (speedup 1.0000x reference)
#include <cuda_runtime.h>
#include <cuda_bf16.h>
#include <math.h>
#include <stdint.h>

#define NTOK 43520   // N * Lq = 8 * 5440
#define LQ 5440
#define DIM 256
#define NHEAD 8
#define HDIM 32
#define NLVL 4
#define NPT 4
#define DFFN 1024

// ---- scratch (static device globals; no runtime allocation) ----
__device__ float g_query[(size_t)NTOK * DIM];    // src2 (outproj result)
__device__ __nv_bfloat16 g_srch[(size_t)NTOK * DIM];     // bf16 src
__device__ __nv_bfloat16 g_queryh[(size_t)NTOK * DIM];   // bf16 (src+pos)
__device__ __nv_bfloat16 g_valueh[(size_t)NTOK * DIM];   // bf16 value for sampling
__device__ float g_oa[(size_t)NTOK * 384];      // fused offsets(256)+attn logits(128)
__device__ __nv_bfloat16 g_attnouth[(size_t)NTOK * DIM]; // deform out (bf16)
__device__ float g_ffnout[(size_t)NTOK * DIM];  // FFN2 out
__device__ float g_x[(size_t)NTOK * DIM];
__device__ __nv_bfloat16 g_xh[(size_t)NTOK * DIM];       // bf16 copy of x for FFN
__device__ __nv_bfloat16 g_hiddenh[(size_t)NTOK * DFFN]; // bf16 FFN hidden
// transposed (K-major) bf16 weights
__device__ __nv_bfloat16 g_WvTh[256 * 256];
__device__ __nv_bfloat16 g_WoaTh[384 * 256];    // rows 0..255 = W_off^T, 256..383 = W_attn^T
__device__ __nv_bfloat16 g_WoutTh[256 * 256];
__device__ __nv_bfloat16 g_W1Th[1024 * 256];
__device__ __nv_bfloat16 g_W2Th[256 * 1024];
__device__ float g_boa[384];

// ---------------------------------------------------------------------------
__device__ __forceinline__ uint32_t s2u(const void* p) {
    uint32_t a;
    asm("{ .reg .u64 t; cvta.to.shared.u64 t, %1; cvt.u32.u64 %0, t; }" : "=r"(a) : "l"(p));
    return a;
}

__device__ __forceinline__ void cp16(uint32_t dst, const void* src) {
    asm volatile("cp.async.cg.shared.global [%0], [%1], 16;" :: "r"(dst), "l"(src));
}

__device__ __forceinline__ void ldsm_x4(uint32_t& r0, uint32_t& r1, uint32_t& r2,
                                        uint32_t& r3, uint32_t addr) {
    asm volatile("ldmatrix.sync.aligned.m8n8.x4.shared.b16 {%0,%1,%2,%3}, [%4];"
                 : "=r"(r0), "=r"(r1), "=r"(r2), "=r"(r3) : "r"(addr));
}

__device__ __forceinline__ void ldsm_x2(uint32_t& r0, uint32_t& r1, uint32_t addr) {
    asm volatile("ldmatrix.sync.aligned.m8n8.x2.shared.b16 {%0,%1}, [%2];"
                 : "=r"(r0), "=r"(r1) : "r"(addr));
}

__device__ __forceinline__ void mma_bf16(float c[4], uint32_t a0, uint32_t a1,
                                         uint32_t a2, uint32_t a3,
                                         uint32_t b0, uint32_t b1) {
    asm volatile(
        "mma.sync.aligned.m16n8k16.row.col.f32.bf16.bf16.f32 "
        "{%0,%1,%2,%3}, {%4,%5,%6,%7}, {%8,%9}, {%0,%1,%2,%3};"
        : "+f"(c[0]), "+f"(c[1]), "+f"(c[2]), "+f"(c[3])
        : "r"(a0), "r"(a1), "r"(a2), "r"(a3), "r"(b0), "r"(b1));
}

// ---------------------------------------------------------------------------
// bf16 GEMM: C = A[M,K] @ Bt[N,K]^T + bias. mode: 0=f32, 1=+relu, 2=bf16 out,
// 3=bf16+relu. CTA tile 128x128, 256 threads (2x4 warps, warp tile 64x32),
// K-chunk 64, 2-stage cp.async pipeline, ldmatrix fragments.
// Stage: 128 rows x 144B per operand, A then B = 36864B; 2 stages = 73728B.
// __launch_bounds__(256,3): 3 CTAs/SM (reg cap 85, smem 3*72KB <= 228KB).
// ---------------------------------------------------------------------------
#define SSTR 36
#define STAGE_B (2 * 128 * SSTR * 4)  // 36864 bytes
#define BOFF_B (128 * SSTR * 4)      // 18432 bytes
#define NSTAGE 2

#define ISSUE(s, kc)                                                          \
    {                                                                         \
        const uint32_t so = sb + (uint32_t)(s) * STAGE_B;                     \
        _Pragma("unroll")                                                     \
        for (int i = 0; i < 4; i++) {                                         \
            const int r = r_ + (i << 5);                                      \
            const uint32_t off = ((uint32_t)(r * SSTR + (q_ << 2))) << 2;     \
            cp16(so + off, Abase + (size_t)r * rowstr + (size_t)(kc) * 8 + q_);\
            cp16(so + BOFF_B + off, Bbase + (size_t)r * rowstr + (size_t)(kc) * 8 + q_);\
        }                                                                     \
        asm volatile("cp.async.commit_group;" ::: "memory");                  \
    }

__global__ __launch_bounds__(256, 3)
void hgemm(const __nv_bfloat16* __restrict__ A, const __nv_bfloat16* __restrict__ Bt,
           const float* __restrict__ bias, void* __restrict__ Cv,
           int M, int N, int K, int mode) {
    extern __shared__ float smem[];
    const uint32_t sb = s2u(smem);
    const int tid = threadIdx.x, wid = tid >> 5, lane = tid & 31;
    const int m0 = blockIdx.y << 7, n0 = blockIdx.x << 7;
    const int warp_m = (wid & 1) * 64;
    const int warp_n = (wid >> 1) * 32;
    const int lr = lane >> 2, lc = lane & 3;

    float c[4][4][4];
#pragma unroll
    for (int i = 0; i < 4; i++)
#pragma unroll
        for (int j = 0; j < 4; j++)
#pragma unroll
            for (int q = 0; q < 4; q++) c[i][j][q] = 0.f;

    const int nk = K >> 6;
    const int rowstr = K >> 3;   // 16B units per source row (bf16)
    const float4* Abase = (const float4*)(A + (size_t)m0 * K);
    const float4* Bbase = (const float4*)(Bt + (size_t)n0 * K);
    const int r_ = tid >> 3, q_ = tid & 7;

    const int quad = lane >> 3, rr = lane & 7;
    uint32_t aoff[4], boff[4];
#pragma unroll
    for (int i = 0; i < 4; i++)
        aoff[i] = (uint32_t)(((warp_m + (i << 4) + ((quad & 1) << 3) + rr) * SSTR
                              + ((quad >> 1) << 2)) << 2);
#pragma unroll
    for (int j = 0; j < 4; j++)
        boff[j] = (uint32_t)(((warp_n + (j << 3) + rr) * SSTR
                              + ((quad & 1) << 2)) << 2) + BOFF_B;

    ISSUE(0, 0);
    if (nk > 1) ISSUE(1, 1);
    int s = 0;
    for (int kc = 0; kc < nk; kc++) {
        if (kc + 1 < nk) {
            asm volatile("cp.async.wait_group 1;" ::: "memory");
        } else {
            asm volatile("cp.async.wait_group 0;" ::: "memory");
        }
        __syncthreads();

        const uint32_t sA = sb + (uint32_t)s * STAGE_B;
#pragma unroll
        for (int ks = 0; ks < 4; ks++) {
            const uint32_t k0b = (uint32_t)ks << 5;
            uint32_t af[4][4], bf[4][2];
#pragma unroll
            for (int i = 0; i < 4; i++)
                ldsm_x4(af[i][0], af[i][1], af[i][2], af[i][3], sA + aoff[i] + k0b);
#pragma unroll
            for (int j = 0; j < 4; j++)
                ldsm_x2(bf[j][0], bf[j][1], sA + boff[j] + k0b);
#pragma unroll
            for (int i = 0; i < 4; i++)
#pragma unroll
                for (int j = 0; j < 4; j++)
                    mma_bf16(c[i][j], af[i][0], af[i][1], af[i][2], af[i][3],
                             bf[j][0], bf[j][1]);
        }
        __syncthreads();
        if (kc + 2 < nk) ISSUE(s, kc + 2);
        s ^= 1;
    }

    // epilogue
#pragma unroll
    for (int i = 0; i < 4; i++) {
        const int r0 = m0 + warp_m + (i << 4) + lr;
#pragma unroll
        for (int j = 0; j < 4; j++) {
            const int c0 = n0 + warp_n + (j << 3) + (lc << 1);
            const float b0 = bias[c0], b1 = bias[c0 + 1];
            float v0 = c[i][j][0] + b0, v1 = c[i][j][1] + b1;
            float v2 = c[i][j][2] + b0, v3 = c[i][j][3] + b1;
            if (mode & 1) {
                v0 = fmaxf(v0, 0.f); v1 = fmaxf(v1, 0.f);
                v2 = fmaxf(v2, 0.f); v3 = fmaxf(v3, 0.f);
            }
            if (mode & 2) {
                __nv_bfloat16* Ch = (__nv_bfloat16*)Cv;
                __nv_bfloat162 p0, p1;
                p0.x = __float2bfloat16_rn(v0); p0.y = __float2bfloat16_rn(v1);
                p1.x = __float2bfloat16_rn(v2); p1.y = __float2bfloat16_rn(v3);
                *(__nv_bfloat162*)(Ch + (size_t)r0 * N + c0) = p0;
                *(__nv_bfloat162*)(Ch + (size_t)(r0 + 8) * N + c0) = p1;
            } else {
                float* C = (float*)Cv;
                *(float2*)(C + (size_t)r0 * N + c0) = make_float2(v0, v1);
                *(float2*)(C + (size_t)(r0 + 8) * N + c0) = make_float2(v2, v3);
            }
        }
    }
}

// ---------------------------------------------------------------------------
// prep: all weight transposes (f32 -> bf16 K-major) + bias concat, one kernel.
// ---------------------------------------------------------------------------
__device__ __forceinline__ void tr_tile_h(float t[32][33],
                                          const float* __restrict__ in,
                                          __nv_bfloat16* __restrict__ out,
                                          int C_in, int out_stride,
                                          int tx, int ty, int orow_off) {
    const int tyid = threadIdx.x >> 5, txid = threadIdx.x & 31;
    t[tyid][txid] = in[(size_t)(ty * 32 + tyid) * C_in + tx * 32 + txid];
    __syncthreads();
    out[(size_t)(orow_off + tx * 32 + tyid) * out_stride + ty * 32 + txid] =
        __float2bfloat16_rn(t[txid][tyid]);
}

__global__ __launch_bounds__(1024)
void prep_w(const float* __restrict__ Wv, const float* __restrict__ Woff,
            const float* __restrict__ Wattn, const float* __restrict__ Wout,
            const float* __restrict__ W1, const float* __restrict__ W2,
            const float* __restrict__ boff, const float* __restrict__ battn) {
    __shared__ float t[32][33];
    const int b = blockIdx.x;
    if (b < 64) {
        tr_tile_h(t, Wv, g_WvTh, 256, 256, b & 7, b >> 3, 0);
    } else if (b < 128) {
        const int l = b - 64;
        tr_tile_h(t, Woff, g_WoaTh, 256, 256, l & 7, l >> 3, 0);
    } else if (b < 160) {
        const int l = b - 128;
        tr_tile_h(t, Wattn, g_WoaTh, 128, 256, l & 3, l >> 2, 256);
    } else if (b < 224) {
        const int l = b - 160;
        tr_tile_h(t, Wout, g_WoutTh, 256, 256, l & 7, l >> 3, 0);
    } else if (b < 480) {
        const int l = b - 224;
        tr_tile_h(t, W1, g_W1Th, 1024, 256, l & 31, l >> 5, 0);
    } else if (b < 736) {
        const int l = b - 480;
        tr_tile_h(t, W2, g_W2Th, 256, 1024, l & 7, l >> 3, 0);
    } else {
        const int tid = threadIdx.x;
        if (tid < 256) g_boa[tid] = boff[tid];
        else if (tid < 384) g_boa[tid] = battn[tid - 256];
    }
}

// ---------------------------------------------------------------------------
// srch = bf16(src); queryh = bf16(src + pos)
// ---------------------------------------------------------------------------
__global__ void add2_kernel(const float4* __restrict__ src, const float4* __restrict__ pos,
                            __nv_bfloat16* __restrict__ srch,
                            __nv_bfloat16* __restrict__ queryh, int n4) {
    int i = blockIdx.x * blockDim.x + threadIdx.x;
    if (i < n4) {
        float4 s = src[i], p = pos[i];
        __nv_bfloat162 s0, s1, q0, q1;
        s0.x = __float2bfloat16_rn(s.x); s0.y = __float2bfloat16_rn(s.y);
        s1.x = __float2bfloat16_rn(s.z); s1.y = __float2bfloat16_rn(s.w);
        q0.x = __float2bfloat16_rn(s.x + p.x); q0.y = __float2bfloat16_rn(s.y + p.y);
        q1.x = __float2bfloat16_rn(s.z + p.z); q1.y = __float2bfloat16_rn(s.w + p.w);
        uint2 us, uq;
        us.x = *(uint32_t*)&s0; us.y = *(uint32_t*)&s1;
        uq.x = *(uint32_t*)&q0; uq.y = *(uint32_t*)&q1;
        *(uint2*)(srch + (size_t)i * 4) = us;
        *(uint2*)(queryh + (size_t)i * 4) = uq;
    }
}

// ---------------------------------------------------------------------------
// deformable attention sampling from bf16 value.
// 256 threads = 8 warps = 4 tokens/block. Each warp serves 4 heads:
// 8 lanes per head, each lane owns 4 consecutive bf16 channels (uint2 load).
// Output bf16 (feeds outproj GEMM A operand).
// ---------------------------------------------------------------------------
__global__ __launch_bounds__(256)
void deform_kernel(const float* __restrict__ refp) {
    const int wid = threadIdx.x >> 5, lane = threadIdx.x & 31;
    const int gw = blockIdx.x * 8 + wid;
    const int m = gw >> 1;
    const int h = ((gw & 1) << 2) + (lane >> 3);
    const int g = lane & 7;
    const int b = m / LQ;

    const int lvlH[NLVL] = {64, 32, 16, 8};
    const int lvlW[NLVL] = {64, 32, 16, 8};
    const int lvlS[NLVL] = {0, 4096, 5120, 5376};

    const float* logit = g_oa + (size_t)m * 384 + 256 + h * 16;
    float mx = -1e30f;
#pragma unroll
    for (int i = 0; i < 16; i++) mx = fmaxf(mx, logit[i]);
    float w[16];
    float sum = 0.f;
#pragma unroll
    for (int i = 0; i < 16; i++) { w[i] = expf(logit[i] - mx); sum += w[i]; }
    const float inv = 1.f / sum;

    const float* off = g_oa + (size_t)m * 384 + h * 32;
    const float* rp = refp + (size_t)m * NLVL * 2;

    float acc0 = 0.f, acc1 = 0.f, acc2 = 0.f, acc3 = 0.f;
#pragma unroll
    for (int l = 0; l < NLVL; l++) {
        const int H = lvlH[l], W = lvlW[l], S = lvlS[l];
        const float rx = rp[l * 2 + 0];
        const float ry = rp[l * 2 + 1];
        const float invW = 1.f / (float)W;
        const float invH = 1.f / (float)H;
        const __nv_bfloat16* vb =
            g_valueh + ((size_t)b * LQ + S) * DIM + h * HDIM + (g << 2);
#pragma unroll
        for (int p = 0; p < NPT; p++) {
            const int oi = (l * NPT + p) * 2;
            const float lx = rx + off[oi + 0] * invW;
            const float ly = ry + off[oi + 1] * invH;
            const float x = lx * (float)W - 0.5f;
            const float y = ly * (float)H - 0.5f;
            const float x0f = floorf(x), y0f = floorf(y);
            const int x0 = (int)x0f, y0 = (int)y0f;
            const float wx1 = x - x0f, wy1 = y - y0f;
            const float wx0 = 1.f - wx1, wy0 = 1.f - wy1;

            const bool xin0 = (x0 >= 0) & (x0 < W);
            const bool xin1 = (x0 + 1 >= 0) & (x0 + 1 < W);
            const bool yin0 = (y0 >= 0) & (y0 < H);
            const bool yin1 = (y0 + 1 >= 0) & (y0 + 1 < H);

            uint2 u00 = make_uint2(0u, 0u), u01 = u00, u10 = u00, u11 = u00;
            if (yin0 & xin0) u00 = *(const uint2*)(vb + (size_t)(y0 * W + x0) * DIM);
            if (yin0 & xin1) u01 = *(const uint2*)(vb + (size_t)(y0 * W + x0 + 1) * DIM);
            if (yin1 & xin0) u10 = *(const uint2*)(vb + (size_t)((y0 + 1) * W + x0) * DIM);
            if (yin1 & xin1) u11 = *(const uint2*)(vb + (size_t)((y0 + 1) * W + x0 + 1) * DIM);

            const float wt = w[l * NPT + p] * inv;
            const float w00 = wt * wx0 * wy0, w01 = wt * wx1 * wy0;
            const float w10 = wt * wx0 * wy1, w11 = wt * wx1 * wy1;

            float2 a0 = __bfloat1622float2(*(__nv_bfloat162*)&u00.x);
            float2 a1 = __bfloat1622float2(*(__nv_bfloat162*)&u00.y);
            float2 b0 = __bfloat1622float2(*(__nv_bfloat162*)&u01.x);
            float2 b1 = __bfloat1622float2(*(__nv_bfloat162*)&u01.y);
            float2 c0 = __bfloat1622float2(*(__nv_bfloat162*)&u10.x);
            float2 c1 = __bfloat1622float2(*(__nv_bfloat162*)&u10.y);
            float2 d0 = __bfloat1622float2(*(__nv_bfloat162*)&u11.x);
            float2 d1 = __bfloat1622float2(*(__nv_bfloat162*)&u11.y);

            acc0 = fmaf(w00, a0.x, fmaf(w01, b0.x, fmaf(w10, c0.x, fmaf(w11, d0.x, acc0))));
            acc1 = fmaf(w00, a0.y, fmaf(w01, b0.y, fmaf(w10, c0.y, fmaf(w11, d0.y, acc1))));
            acc2 = fmaf(w00, a1.x, fmaf(w01, b1.x, fmaf(w10, c1.x, fmaf(w11, d1.x, acc2))));
            acc3 = fmaf(w00, a1.y, fmaf(w01, b1.y, fmaf(w10, c1.y, fmaf(w11, d1.y, acc3))));
        }
    }
    __nv_bfloat162 p0, p1;
    p0.x = __float2bfloat16_rn(acc0); p0.y = __float2bfloat16_rn(acc1);
    p1.x = __float2bfloat16_rn(acc2); p1.y = __float2bfloat16_rn(acc3);
    uint2 st;
    st.x = *(uint32_t*)&p0; st.y = *(uint32_t*)&p1;
    *(uint2*)(g_attnouth + (size_t)m * DIM + h * HDIM + (g << 2)) = st;
}

// ---------------------------------------------------------------------------
// fused residual + LayerNorm; optional extra bf16 output
// ---------------------------------------------------------------------------
__global__ __launch_bounds__(256)
void ln_kernel(const float* __restrict__ a, const float* __restrict__ b,
               const float* __restrict__ gam, const float* __restrict__ bet,
               float* __restrict__ o, __nv_bfloat16* __restrict__ oh) {
    __shared__ float sred[8];
    __shared__ float smu, svar;
    const int m = blockIdx.x;
    const int t = threadIdx.x;
    const size_t idx = (size_t)m * DIM + t;
    const float v = a[idx] + b[idx];

    float s = v;
#pragma unroll
    for (int off = 16; off > 0; off >>= 1) s += __shfl_xor_sync(0xffffffffu, s, off);
    if ((t & 31) == 0) sred[t >> 5] = s;
    __syncthreads();
    if (t == 0) {
        float tot = 0.f;
#pragma unroll
        for (int i = 0; i < 8; i++) tot += sred[i];
        smu = tot * (1.f / DIM);
    }
    __syncthreads();
    const float mu = smu;
    const float d = v - mu;

    s = d * d;
#pragma unroll
    for (int off = 16; off > 0; off >>= 1) s += __shfl_xor_sync(0xffffffffu, s, off);
    if ((t & 31) == 0) sred[t >> 5] = s;
    __syncthreads();
    if (t == 0) {
        float tot = 0.f;
#pragma unroll
        for (int i = 0; i < 8; i++) tot += sred[i];
        svar = tot * (1.f / DIM);
    }
    __syncthreads();

    const float r = d * rsqrtf(svar + 1e-5f) * gam[t] + bet[t];
    o[idx] = r;
    if (oh) oh[idx] = __float2bfloat16_rn(r);
}

// ---------------------------------------------------------------------------
extern "C" void kernel_launch(void* const* d_in, const int* in_sizes, int n_in,
                              void* d_out, int out_size) {
    const float* src    = (const float*)d_in[0];
    const float* pos    = (const float*)d_in[1];
    const float* refp   = (const float*)d_in[2];
    const float* W_value = (const float*)d_in[4];
    const float* b_value = (const float*)d_in[5];
    const float* W_off   = (const float*)d_in[6];
    const float* b_off   = (const float*)d_in[7];
    const float* W_attn  = (const float*)d_in[8];
    const float* b_attn  = (const float*)d_in[9];
    const float* W_out   = (const float*)d_in[10];
    const float* b_out   = (const float*)d_in[11];
    const float* ln1g    = (const float*)d_in[12];
    const float* ln1b    = (const float*)d_in[13];
    const float* W1      = (const float*)d_in[14];
    const float* b1      = (const float*)d_in[15];
    const float* W2      = (const float*)d_in[16];
    const float* b2      = (const float*)d_in[17];
    const float* ln2g    = (const float*)d_in[18];
    const float* ln2b    = (const float*)d_in[19];
    float* out = (float*)d_out;

    float *query, *oa, *ffnout, *x, *boa;
    __nv_bfloat16 *srch, *queryh, *valueh, *attnouth, *xh, *hiddenh;
    __nv_bfloat16 *WvTh, *WoaTh, *WoutTh, *W1Th, *W2Th;
    cudaGetSymbolAddress((void**)&query,    g_query);
    cudaGetSymbolAddress((void**)&srch,     g_srch);
    cudaGetSymbolAddress((void**)&queryh,   g_queryh);
    cudaGetSymbolAddress((void**)&valueh,   g_valueh);
    cudaGetSymbolAddress((void**)&oa,       g_oa);
    cudaGetSymbolAddress((void**)&attnouth, g_attnouth);
    cudaGetSymbolAddress((void**)&ffnout,   g_ffnout);
    cudaGetSymbolAddress((void**)&x,        g_x);
    cudaGetSymbolAddress((void**)&xh,       g_xh);
    cudaGetSymbolAddress((void**)&hiddenh,  g_hiddenh);
    cudaGetSymbolAddress((void**)&WvTh,  g_WvTh);
    cudaGetSymbolAddress((void**)&WoaTh, g_WoaTh);
    cudaGetSymbolAddress((void**)&WoutTh, g_WoutTh);
    cudaGetSymbolAddress((void**)&W1Th,  g_W1Th);
    cudaGetSymbolAddress((void**)&W2Th,  g_W2Th);
    cudaGetSymbolAddress((void**)&boa,   g_boa);

    const int SMEM = NSTAGE * STAGE_B;   // 73728
    cudaFuncSetAttribute(hgemm, cudaFuncAttributeMaxDynamicSharedMemorySize, SMEM);

    const int M = NTOK;
    const int n4 = NTOK * DIM / 4;

    // 1: weight prep (bf16 transposed)
    prep_w<<<737, 1024>>>(W_value, W_off, W_attn, W_out, W1, W2, b_off, b_attn);

    // 2: srch = bf16(src); queryh = bf16(src + pos)
    add2_kernel<<<(n4 + 255) / 256, 256>>>((const float4*)src, (const float4*)pos,
                                           srch, queryh, n4);

    // 3: value projection (bf16 in/out)
    hgemm<<<dim3(2, M / 128), 256, SMEM>>>(srch, WvTh, b_value, valueh, M, DIM, DIM, 2);
    // 4: fused offsets+attn projection (N=384, f32 out)
    hgemm<<<dim3(3, M / 128), 256, SMEM>>>(queryh, WoaTh, boa, oa, M, 384, DIM, 0);

    // 5: deformable sampling + attention-weighted sum -> bf16
    deform_kernel<<<M / 4, 256>>>(refp);

    // 6: output projection -> src2 f32
    hgemm<<<dim3(2, M / 128), 256, SMEM>>>(attnouth, WoutTh, b_out, query, M, DIM, DIM, 0);

    // 7: x = LN(src + src2), also bf16 copy for FFN
    ln_kernel<<<M, 256>>>(src, query, ln1g, ln1b, x, xh);

    // 8-9: FFN in bf16 (hidden bf16+relu; FFN2 f32 out)
    hgemm<<<dim3(8, M / 128), 256, SMEM>>>(xh,      W1Th, b1, hiddenh, M, DFFN, DIM, 3);
    hgemm<<<dim3(2, M / 128), 256, SMEM>>>(hiddenh, W2Th, b2, ffnout,  M, DIM, DFFN, 0);

    // 10: out = LN(x + ffn)
    ln_kernel<<<M, 256>>>(x, ffnout, ln2g, ln2b, out, nullptr);
}

// round 14
// speedup vs baseline: 1.8198x; 1.8198x over previous
#include <cuda_runtime.h>
#include <cuda_bf16.h>
#include <math.h>
#include <stdint.h>

#define NTOK 43520   // N * Lq = 8 * 5440
#define LQ 5440
#define DIM 256
#define NHEAD 8
#define HDIM 32
#define NLVL 4
#define NPT 4
#define DFFN 1024

// ---- scratch (static device globals; no runtime allocation) ----
__device__ float g_query[(size_t)NTOK * DIM];    // src2 (outproj result)
__device__ __nv_bfloat16 g_srch[(size_t)NTOK * DIM];     // bf16 src
__device__ __nv_bfloat16 g_queryh[(size_t)NTOK * DIM];   // bf16 (src+pos)
__device__ __nv_bfloat16 g_valueh[(size_t)NTOK * DIM];   // bf16 value for sampling
__device__ float g_oa[(size_t)NTOK * 384];      // fused offsets(256)+attn logits(128)
__device__ __nv_bfloat16 g_attnouth[(size_t)NTOK * DIM]; // deform out (bf16)
__device__ float g_ffnout[(size_t)NTOK * DIM];  // FFN2 out
__device__ float g_x[(size_t)NTOK * DIM];
__device__ __nv_bfloat16 g_xh[(size_t)NTOK * DIM];       // bf16 copy of x for FFN
__device__ __nv_bfloat16 g_hiddenh[(size_t)NTOK * DFFN]; // bf16 FFN hidden
// transposed (K-major) bf16 weights
__device__ __nv_bfloat16 g_WvTh[256 * 256];
__device__ __nv_bfloat16 g_WoaTh[384 * 256];    // rows 0..255 = W_off^T, 256..383 = W_attn^T
__device__ __nv_bfloat16 g_WoutTh[256 * 256];
__device__ __nv_bfloat16 g_W1Th[1024 * 256];
__device__ __nv_bfloat16 g_W2Th[256 * 1024];
__device__ float g_boa[384];

// ---------------------------------------------------------------------------
__device__ __forceinline__ uint32_t s2u(const void* p) {
    uint32_t a;
    asm("{ .reg .u64 t; cvta.to.shared.u64 t, %1; cvt.u32.u64 %0, t; }" : "=r"(a) : "l"(p));
    return a;
}

__device__ __forceinline__ void cp16(uint32_t dst, const void* src) {
    asm volatile("cp.async.cg.shared.global [%0], [%1], 16;" :: "r"(dst), "l"(src));
}

__device__ __forceinline__ void ldsm_x4(uint32_t& r0, uint32_t& r1, uint32_t& r2,
                                        uint32_t& r3, uint32_t addr) {
    asm volatile("ldmatrix.sync.aligned.m8n8.x4.shared.b16 {%0,%1,%2,%3}, [%4];"
                 : "=r"(r0), "=r"(r1), "=r"(r2), "=r"(r3) : "r"(addr));
}

__device__ __forceinline__ void ldsm_x2(uint32_t& r0, uint32_t& r1, uint32_t addr) {
    asm volatile("ldmatrix.sync.aligned.m8n8.x2.shared.b16 {%0,%1}, [%2];"
                 : "=r"(r0), "=r"(r1) : "r"(addr));
}

__device__ __forceinline__ void mma_bf16(float c[4], uint32_t a0, uint32_t a1,
                                         uint32_t a2, uint32_t a3,
                                         uint32_t b0, uint32_t b1) {
    asm volatile(
        "mma.sync.aligned.m16n8k16.row.col.f32.bf16.bf16.f32 "
        "{%0,%1,%2,%3}, {%4,%5,%6,%7}, {%8,%9}, {%0,%1,%2,%3};"
        : "+f"(c[0]), "+f"(c[1]), "+f"(c[2]), "+f"(c[3])
        : "r"(a0), "r"(a1), "r"(a2), "r"(a3), "r"(b0), "r"(b1));
}

// ---------------------------------------------------------------------------
// bf16 GEMM: C = A[M,K] @ Bt[N,K]^T + bias. mode: 0=f32, 1=+relu, 2=bf16 out,
// 3=bf16+relu. CTA tile 128x128, 256 threads (2x4 warps, warp tile 64x32),
// K-chunk 64, 3-stage cp.async pipeline, ldmatrix fragments.
// Single barrier per chunk: wait -> sync -> issue(kc+2) -> compute. The issue
// targets the stage consumed at kc-1; the barrier proves all warps finished
// that compute, so no trailing sync is needed.
// Stage: 128 rows x 144B per operand, A then B = 36864B; 3 stages = 110592B.
// ---------------------------------------------------------------------------
#define SSTR 36
#define STAGE_B (2 * 128 * SSTR * 4)  // 36864 bytes
#define BOFF_B (128 * SSTR * 4)      // 18432 bytes
#define NSTAGE 3

#define ISSUE(s, kc)                                                          \
    {                                                                         \
        const uint32_t so = sb + (uint32_t)(s) * STAGE_B;                     \
        _Pragma("unroll")                                                     \
        for (int i = 0; i < 4; i++) {                                         \
            const int r = r_ + (i << 5);                                      \
            const uint32_t off = ((uint32_t)(r * SSTR + (q_ << 2))) << 2;     \
            cp16(so + off, Abase + (size_t)r * rowstr + (size_t)(kc) * 8 + q_);\
            cp16(so + BOFF_B + off, Bbase + (size_t)r * rowstr + (size_t)(kc) * 8 + q_);\
        }                                                                     \
        asm volatile("cp.async.commit_group;" ::: "memory");                  \
    }

__global__ __launch_bounds__(256)
void hgemm(const __nv_bfloat16* __restrict__ A, const __nv_bfloat16* __restrict__ Bt,
           const float* __restrict__ bias, void* __restrict__ Cv,
           int M, int N, int K, int mode) {
    extern __shared__ float smem[];
    const uint32_t sb = s2u(smem);
    const int tid = threadIdx.x, wid = tid >> 5, lane = tid & 31;
    const int m0 = blockIdx.y << 7, n0 = blockIdx.x << 7;
    const int warp_m = (wid & 1) * 64;
    const int warp_n = (wid >> 1) * 32;
    const int lr = lane >> 2, lc = lane & 3;

    float c[4][4][4];
#pragma unroll
    for (int i = 0; i < 4; i++)
#pragma unroll
        for (int j = 0; j < 4; j++)
#pragma unroll
            for (int q = 0; q < 4; q++) c[i][j][q] = 0.f;

    const int nk = K >> 6;
    const int rowstr = K >> 3;   // 16B units per source row (bf16)
    const float4* Abase = (const float4*)(A + (size_t)m0 * K);
    const float4* Bbase = (const float4*)(Bt + (size_t)n0 * K);
    const int r_ = tid >> 3, q_ = tid & 7;

    const int quad = lane >> 3, rr = lane & 7;
    uint32_t aoff[4], boff[4];
#pragma unroll
    for (int i = 0; i < 4; i++)
        aoff[i] = (uint32_t)(((warp_m + (i << 4) + ((quad & 1) << 3) + rr) * SSTR
                              + ((quad >> 1) << 2)) << 2);
#pragma unroll
    for (int j = 0; j < 4; j++)
        boff[j] = (uint32_t)(((warp_n + (j << 3) + rr) * SSTR
                              + ((quad & 1) << 2)) << 2) + BOFF_B;

    ISSUE(0, 0);
    if (nk > 1) ISSUE(1, 1);
    int s = 0;
    for (int kc = 0; kc < nk; kc++) {
        if (kc + 1 < nk) {
            asm volatile("cp.async.wait_group 1;" ::: "memory");
        } else {
            asm volatile("cp.async.wait_group 0;" ::: "memory");
        }
        __syncthreads();
        if (kc + 2 < nk) {
            int sn = s + 2; if (sn >= NSTAGE) sn -= NSTAGE;
            ISSUE(sn, kc + 2);
        }

        const uint32_t sA = sb + (uint32_t)s * STAGE_B;
#pragma unroll
        for (int ks = 0; ks < 4; ks++) {
            const uint32_t k0b = (uint32_t)ks << 5;
            uint32_t af[4][4], bf[4][2];
#pragma unroll
            for (int i = 0; i < 4; i++)
                ldsm_x4(af[i][0], af[i][1], af[i][2], af[i][3], sA + aoff[i] + k0b);
#pragma unroll
            for (int j = 0; j < 4; j++)
                ldsm_x2(bf[j][0], bf[j][1], sA + boff[j] + k0b);
#pragma unroll
            for (int i = 0; i < 4; i++)
#pragma unroll
                for (int j = 0; j < 4; j++)
                    mma_bf16(c[i][j], af[i][0], af[i][1], af[i][2], af[i][3],
                             bf[j][0], bf[j][1]);
        }
        if (++s >= NSTAGE) s = 0;
    }

    // epilogue
#pragma unroll
    for (int i = 0; i < 4; i++) {
        const int r0 = m0 + warp_m + (i << 4) + lr;
#pragma unroll
        for (int j = 0; j < 4; j++) {
            const int c0 = n0 + warp_n + (j << 3) + (lc << 1);
            const float b0 = bias[c0], b1 = bias[c0 + 1];
            float v0 = c[i][j][0] + b0, v1 = c[i][j][1] + b1;
            float v2 = c[i][j][2] + b0, v3 = c[i][j][3] + b1;
            if (mode & 1) {
                v0 = fmaxf(v0, 0.f); v1 = fmaxf(v1, 0.f);
                v2 = fmaxf(v2, 0.f); v3 = fmaxf(v3, 0.f);
            }
            if (mode & 2) {
                __nv_bfloat16* Ch = (__nv_bfloat16*)Cv;
                __nv_bfloat162 p0, p1;
                p0.x = __float2bfloat16_rn(v0); p0.y = __float2bfloat16_rn(v1);
                p1.x = __float2bfloat16_rn(v2); p1.y = __float2bfloat16_rn(v3);
                *(__nv_bfloat162*)(Ch + (size_t)r0 * N + c0) = p0;
                *(__nv_bfloat162*)(Ch + (size_t)(r0 + 8) * N + c0) = p1;
            } else {
                float* C = (float*)Cv;
                *(float2*)(C + (size_t)r0 * N + c0) = make_float2(v0, v1);
                *(float2*)(C + (size_t)(r0 + 8) * N + c0) = make_float2(v2, v3);
            }
        }
    }
}

// ---------------------------------------------------------------------------
// prep: all weight transposes (f32 -> bf16 K-major) + bias concat, one kernel.
// ---------------------------------------------------------------------------
__device__ __forceinline__ void tr_tile_h(float t[32][33],
                                          const float* __restrict__ in,
                                          __nv_bfloat16* __restrict__ out,
                                          int C_in, int out_stride,
                                          int tx, int ty, int orow_off) {
    const int tyid = threadIdx.x >> 5, txid = threadIdx.x & 31;
    t[tyid][txid] = in[(size_t)(ty * 32 + tyid) * C_in + tx * 32 + txid];
    __syncthreads();
    out[(size_t)(orow_off + tx * 32 + tyid) * out_stride + ty * 32 + txid] =
        __float2bfloat16_rn(t[txid][tyid]);
}

__global__ __launch_bounds__(1024)
void prep_w(const float* __restrict__ Wv, const float* __restrict__ Woff,
            const float* __restrict__ Wattn, const float* __restrict__ Wout,
            const float* __restrict__ W1, const float* __restrict__ W2,
            const float* __restrict__ boff, const float* __restrict__ battn) {
    __shared__ float t[32][33];
    const int b = blockIdx.x;
    if (b < 64) {
        tr_tile_h(t, Wv, g_WvTh, 256, 256, b & 7, b >> 3, 0);
    } else if (b < 128) {
        const int l = b - 64;
        tr_tile_h(t, Woff, g_WoaTh, 256, 256, l & 7, l >> 3, 0);
    } else if (b < 160) {
        const int l = b - 128;
        tr_tile_h(t, Wattn, g_WoaTh, 128, 256, l & 3, l >> 2, 256);
    } else if (b < 224) {
        const int l = b - 160;
        tr_tile_h(t, Wout, g_WoutTh, 256, 256, l & 7, l >> 3, 0);
    } else if (b < 480) {
        const int l = b - 224;
        tr_tile_h(t, W1, g_W1Th, 1024, 256, l & 31, l >> 5, 0);
    } else if (b < 736) {
        const int l = b - 480;
        tr_tile_h(t, W2, g_W2Th, 256, 1024, l & 7, l >> 3, 0);
    } else {
        const int tid = threadIdx.x;
        if (tid < 256) g_boa[tid] = boff[tid];
        else if (tid < 384) g_boa[tid] = battn[tid - 256];
    }
}

// ---------------------------------------------------------------------------
// srch = bf16(src); queryh = bf16(src + pos)
// ---------------------------------------------------------------------------
__global__ void add2_kernel(const float4* __restrict__ src, const float4* __restrict__ pos,
                            __nv_bfloat16* __restrict__ srch,
                            __nv_bfloat16* __restrict__ queryh, int n4) {
    int i = blockIdx.x * blockDim.x + threadIdx.x;
    if (i < n4) {
        float4 s = src[i], p = pos[i];
        __nv_bfloat162 s0, s1, q0, q1;
        s0.x = __float2bfloat16_rn(s.x); s0.y = __float2bfloat16_rn(s.y);
        s1.x = __float2bfloat16_rn(s.z); s1.y = __float2bfloat16_rn(s.w);
        q0.x = __float2bfloat16_rn(s.x + p.x); q0.y = __float2bfloat16_rn(s.y + p.y);
        q1.x = __float2bfloat16_rn(s.z + p.z); q1.y = __float2bfloat16_rn(s.w + p.w);
        uint2 us, uq;
        us.x = *(uint32_t*)&s0; us.y = *(uint32_t*)&s1;
        uq.x = *(uint32_t*)&q0; uq.y = *(uint32_t*)&q1;
        *(uint2*)(srch + (size_t)i * 4) = us;
        *(uint2*)(queryh + (size_t)i * 4) = uq;
    }
}

// ---------------------------------------------------------------------------
// deformable attention sampling from bf16 value.
// 256 threads = 8 warps = 4 tokens/block. Each warp serves 4 heads:
// 8 lanes per head, each lane owns 4 consecutive bf16 channels (uint2 load).
// Output bf16 (feeds outproj GEMM A operand).
// ---------------------------------------------------------------------------
__global__ __launch_bounds__(256)
void deform_kernel(const float* __restrict__ refp) {
    const int wid = threadIdx.x >> 5, lane = threadIdx.x & 31;
    const int gw = blockIdx.x * 8 + wid;
    const int m = gw >> 1;
    const int h = ((gw & 1) << 2) + (lane >> 3);
    const int g = lane & 7;
    const int b = m / LQ;

    const int lvlH[NLVL] = {64, 32, 16, 8};
    const int lvlW[NLVL] = {64, 32, 16, 8};
    const int lvlS[NLVL] = {0, 4096, 5120, 5376};

    const float* logit = g_oa + (size_t)m * 384 + 256 + h * 16;
    float mx = -1e30f;
#pragma unroll
    for (int i = 0; i < 16; i++) mx = fmaxf(mx, logit[i]);
    float w[16];
    float sum = 0.f;
#pragma unroll
    for (int i = 0; i < 16; i++) { w[i] = expf(logit[i] - mx); sum += w[i]; }
    const float inv = 1.f / sum;

    const float* off = g_oa + (size_t)m * 384 + h * 32;
    const float* rp = refp + (size_t)m * NLVL * 2;

    float acc0 = 0.f, acc1 = 0.f, acc2 = 0.f, acc3 = 0.f;
#pragma unroll
    for (int l = 0; l < NLVL; l++) {
        const int H = lvlH[l], W = lvlW[l], S = lvlS[l];
        const float rx = rp[l * 2 + 0];
        const float ry = rp[l * 2 + 1];
        const float invW = 1.f / (float)W;
        const float invH = 1.f / (float)H;
        const __nv_bfloat16* vb =
            g_valueh + ((size_t)b * LQ + S) * DIM + h * HDIM + (g << 2);
#pragma unroll
        for (int p = 0; p < NPT; p++) {
            const int oi = (l * NPT + p) * 2;
            const float lx = rx + off[oi + 0] * invW;
            const float ly = ry + off[oi + 1] * invH;
            const float x = lx * (float)W - 0.5f;
            const float y = ly * (float)H - 0.5f;
            const float x0f = floorf(x), y0f = floorf(y);
            const int x0 = (int)x0f, y0 = (int)y0f;
            const float wx1 = x - x0f, wy1 = y - y0f;
            const float wx0 = 1.f - wx1, wy0 = 1.f - wy1;

            const bool xin0 = (x0 >= 0) & (x0 < W);
            const bool xin1 = (x0 + 1 >= 0) & (x0 + 1 < W);
            const bool yin0 = (y0 >= 0) & (y0 < H);
            const bool yin1 = (y0 + 1 >= 0) & (y0 + 1 < H);

            uint2 u00 = make_uint2(0u, 0u), u01 = u00, u10 = u00, u11 = u00;
            if (yin0 & xin0) u00 = *(const uint2*)(vb + (size_t)(y0 * W + x0) * DIM);
            if (yin0 & xin1) u01 = *(const uint2*)(vb + (size_t)(y0 * W + x0 + 1) * DIM);
            if (yin1 & xin0) u10 = *(const uint2*)(vb + (size_t)((y0 + 1) * W + x0) * DIM);
            if (yin1 & xin1) u11 = *(const uint2*)(vb + (size_t)((y0 + 1) * W + x0 + 1) * DIM);

            const float wt = w[l * NPT + p] * inv;
            const float w00 = wt * wx0 * wy0, w01 = wt * wx1 * wy0;
            const float w10 = wt * wx0 * wy1, w11 = wt * wx1 * wy1;

            float2 a0 = __bfloat1622float2(*(__nv_bfloat162*)&u00.x);
            float2 a1 = __bfloat1622float2(*(__nv_bfloat162*)&u00.y);
            float2 b0 = __bfloat1622float2(*(__nv_bfloat162*)&u01.x);
            float2 b1 = __bfloat1622float2(*(__nv_bfloat162*)&u01.y);
            float2 c0 = __bfloat1622float2(*(__nv_bfloat162*)&u10.x);
            float2 c1 = __bfloat1622float2(*(__nv_bfloat162*)&u10.y);
            float2 d0 = __bfloat1622float2(*(__nv_bfloat162*)&u11.x);
            float2 d1 = __bfloat1622float2(*(__nv_bfloat162*)&u11.y);

            acc0 = fmaf(w00, a0.x, fmaf(w01, b0.x, fmaf(w10, c0.x, fmaf(w11, d0.x, acc0))));
            acc1 = fmaf(w00, a0.y, fmaf(w01, b0.y, fmaf(w10, c0.y, fmaf(w11, d0.y, acc1))));
            acc2 = fmaf(w00, a1.x, fmaf(w01, b1.x, fmaf(w10, c1.x, fmaf(w11, d1.x, acc2))));
            acc3 = fmaf(w00, a1.y, fmaf(w01, b1.y, fmaf(w10, c1.y, fmaf(w11, d1.y, acc3))));
        }
    }
    __nv_bfloat162 p0, p1;
    p0.x = __float2bfloat16_rn(acc0); p0.y = __float2bfloat16_rn(acc1);
    p1.x = __float2bfloat16_rn(acc2); p1.y = __float2bfloat16_rn(acc3);
    uint2 st;
    st.x = *(uint32_t*)&p0; st.y = *(uint32_t*)&p1;
    *(uint2*)(g_attnouth + (size_t)m * DIM + h * HDIM + (g << 2)) = st;
}

// ---------------------------------------------------------------------------
// fused residual + LayerNorm; optional extra bf16 output
// ---------------------------------------------------------------------------
__global__ __launch_bounds__(256)
void ln_kernel(const float* __restrict__ a, const float* __restrict__ b,
               const float* __restrict__ gam, const float* __restrict__ bet,
               float* __restrict__ o, __nv_bfloat16* __restrict__ oh) {
    __shared__ float sred[8];
    __shared__ float smu, svar;
    const int m = blockIdx.x;
    const int t = threadIdx.x;
    const size_t idx = (size_t)m * DIM + t;
    const float v = a[idx] + b[idx];

    float s = v;
#pragma unroll
    for (int off = 16; off > 0; off >>= 1) s += __shfl_xor_sync(0xffffffffu, s, off);
    if ((t & 31) == 0) sred[t >> 5] = s;
    __syncthreads();
    if (t == 0) {
        float tot = 0.f;
#pragma unroll
        for (int i = 0; i < 8; i++) tot += sred[i];
        smu = tot * (1.f / DIM);
    }
    __syncthreads();
    const float mu = smu;
    const float d = v - mu;

    s = d * d;
#pragma unroll
    for (int off = 16; off > 0; off >>= 1) s += __shfl_xor_sync(0xffffffffu, s, off);
    if ((t & 31) == 0) sred[t >> 5] = s;
    __syncthreads();
    if (t == 0) {
        float tot = 0.f;
#pragma unroll
        for (int i = 0; i < 8; i++) tot += sred[i];
        svar = tot * (1.f / DIM);
    }
    __syncthreads();

    const float r = d * rsqrtf(svar + 1e-5f) * gam[t] + bet[t];
    o[idx] = r;
    if (oh) oh[idx] = __float2bfloat16_rn(r);
}

// ---------------------------------------------------------------------------
extern "C" void kernel_launch(void* const* d_in, const int* in_sizes, int n_in,
                              void* d_out, int out_size) {
    const float* src    = (const float*)d_in[0];
    const float* pos    = (const float*)d_in[1];
    const float* refp   = (const float*)d_in[2];
    const float* W_value = (const float*)d_in[4];
    const float* b_value = (const float*)d_in[5];
    const float* W_off   = (const float*)d_in[6];
    const float* b_off   = (const float*)d_in[7];
    const float* W_attn  = (const float*)d_in[8];
    const float* b_attn  = (const float*)d_in[9];
    const float* W_out   = (const float*)d_in[10];
    const float* b_out   = (const float*)d_in[11];
    const float* ln1g    = (const float*)d_in[12];
    const float* ln1b    = (const float*)d_in[13];
    const float* W1      = (const float*)d_in[14];
    const float* b1      = (const float*)d_in[15];
    const float* W2      = (const float*)d_in[16];
    const float* b2      = (const float*)d_in[17];
    const float* ln2g    = (const float*)d_in[18];
    const float* ln2b    = (const float*)d_in[19];
    float* out = (float*)d_out;

    float *query, *oa, *ffnout, *x, *boa;
    __nv_bfloat16 *srch, *queryh, *valueh, *attnouth, *xh, *hiddenh;
    __nv_bfloat16 *WvTh, *WoaTh, *WoutTh, *W1Th, *W2Th;
    cudaGetSymbolAddress((void**)&query,    g_query);
    cudaGetSymbolAddress((void**)&srch,     g_srch);
    cudaGetSymbolAddress((void**)&queryh,   g_queryh);
    cudaGetSymbolAddress((void**)&valueh,   g_valueh);
    cudaGetSymbolAddress((void**)&oa,       g_oa);
    cudaGetSymbolAddress((void**)&attnouth, g_attnouth);
    cudaGetSymbolAddress((void**)&ffnout,   g_ffnout);
    cudaGetSymbolAddress((void**)&x,        g_x);
    cudaGetSymbolAddress((void**)&xh,       g_xh);
    cudaGetSymbolAddress((void**)&hiddenh,  g_hiddenh);
    cudaGetSymbolAddress((void**)&WvTh,  g_WvTh);
    cudaGetSymbolAddress((void**)&WoaTh, g_WoaTh);
    cudaGetSymbolAddress((void**)&WoutTh, g_WoutTh);
    cudaGetSymbolAddress((void**)&W1Th,  g_W1Th);
    cudaGetSymbolAddress((void**)&W2Th,  g_W2Th);
    cudaGetSymbolAddress((void**)&boa,   g_boa);

    const int SMEM = NSTAGE * STAGE_B;   // 110592
    cudaFuncSetAttribute(hgemm, cudaFuncAttributeMaxDynamicSharedMemorySize, SMEM);

    const int M = NTOK;
    const int n4 = NTOK * DIM / 4;

    // 1: weight prep (bf16 transposed)
    prep_w<<<737, 1024>>>(W_value, W_off, W_attn, W_out, W1, W2, b_off, b_attn);

    // 2: srch = bf16(src); queryh = bf16(src + pos)
    add2_kernel<<<(n4 + 255) / 256, 256>>>((const float4*)src, (const float4*)pos,
                                           srch, queryh, n4);

    // 3: value projection (bf16 in/out)
    hgemm<<<dim3(2, M / 128), 256, SMEM>>>(srch, WvTh, b_value, valueh, M, DIM, DIM, 2);
    // 4: fused offsets+attn projection (N=384, f32 out)
    hgemm<<<dim3(3, M / 128), 256, SMEM>>>(queryh, WoaTh, boa, oa, M, 384, DIM, 0);

    // 5: deformable sampling + attention-weighted sum -> bf16
    deform_kernel<<<M / 4, 256>>>(refp);

    // 6: output projection -> src2 f32
    hgemm<<<dim3(2, M / 128), 256, SMEM>>>(attnouth, WoutTh, b_out, query, M, DIM, DIM, 0);

    // 7: x = LN(src + src2), also bf16 copy for FFN
    ln_kernel<<<M, 256>>>(src, query, ln1g, ln1b, x, xh);

    // 8-9: FFN in bf16 (hidden bf16+relu; FFN2 f32 out)
    hgemm<<<dim3(8, M / 128), 256, SMEM>>>(xh,      W1Th, b1, hiddenh, M, DFFN, DIM, 3);
    hgemm<<<dim3(2, M / 128), 256, SMEM>>>(hiddenh, W2Th, b2, ffnout,  M, DIM, DFFN, 0);

    // 10: out = LN(x + ffn)
    ln_kernel<<<M, 256>>>(x, ffnout, ln2g, ln2b, out, nullptr);
}

// round 15
// speedup vs baseline: 2.0389x; 1.1204x over previous
#include <cuda_runtime.h>
#include <cuda_bf16.h>
#include <math.h>
#include <stdint.h>

#define NTOK 43520   // N * Lq = 8 * 5440
#define LQ 5440
#define DIM 256
#define NHEAD 8
#define HDIM 32
#define NLVL 4
#define NPT 4
#define DFFN 1024

// ---- scratch (static device globals; no runtime allocation) ----
__device__ float g_query[(size_t)NTOK * DIM];    // src2 (outproj result)
__device__ __nv_bfloat16 g_srch[(size_t)NTOK * DIM];     // bf16 src
__device__ __nv_bfloat16 g_queryh[(size_t)NTOK * DIM];   // bf16 (src+pos)
__device__ __nv_bfloat16 g_valueh[(size_t)NTOK * DIM];   // bf16 value for sampling
__device__ float g_oa[(size_t)NTOK * 384];      // fused offsets(256)+attn logits(128)
__device__ __nv_bfloat16 g_attnouth[(size_t)NTOK * DIM]; // deform out (bf16)
__device__ float g_ffnout[(size_t)NTOK * DIM];  // FFN2 out
__device__ float g_x[(size_t)NTOK * DIM];
__device__ __nv_bfloat16 g_xh[(size_t)NTOK * DIM];       // bf16 copy of x for FFN
__device__ __nv_bfloat16 g_hiddenh[(size_t)NTOK * DFFN]; // bf16 FFN hidden
// transposed (K-major) bf16 weights
__device__ __nv_bfloat16 g_WvTh[256 * 256];
__device__ __nv_bfloat16 g_WoaTh[384 * 256];    // rows 0..255 = W_off^T, 256..383 = W_attn^T
__device__ __nv_bfloat16 g_WoutTh[256 * 256];
__device__ __nv_bfloat16 g_W1Th[1024 * 256];
__device__ __nv_bfloat16 g_W2Th[256 * 1024];
__device__ float g_boa[384];

// ---------------------------------------------------------------------------
__device__ __forceinline__ uint32_t s2u(const void* p) {
    uint32_t a;
    asm("{ .reg .u64 t; cvta.to.shared.u64 t, %1; cvt.u32.u64 %0, t; }" : "=r"(a) : "l"(p));
    return a;
}

__device__ __forceinline__ void cp16(uint32_t dst, const void* src) {
    asm volatile("cp.async.cg.shared.global [%0], [%1], 16;" :: "r"(dst), "l"(src));
}

__device__ __forceinline__ void ldsm_x4(uint32_t& r0, uint32_t& r1, uint32_t& r2,
                                        uint32_t& r3, uint32_t addr) {
    asm volatile("ldmatrix.sync.aligned.m8n8.x4.shared.b16 {%0,%1,%2,%3}, [%4];"
                 : "=r"(r0), "=r"(r1), "=r"(r2), "=r"(r3) : "r"(addr));
}

__device__ __forceinline__ void ldsm_x2(uint32_t& r0, uint32_t& r1, uint32_t addr) {
    asm volatile("ldmatrix.sync.aligned.m8n8.x2.shared.b16 {%0,%1}, [%2];"
                 : "=r"(r0), "=r"(r1) : "r"(addr));
}

__device__ __forceinline__ void mma_bf16(float c[4], uint32_t a0, uint32_t a1,
                                         uint32_t a2, uint32_t a3,
                                         uint32_t b0, uint32_t b1) {
    asm volatile(
        "mma.sync.aligned.m16n8k16.row.col.f32.bf16.bf16.f32 "
        "{%0,%1,%2,%3}, {%4,%5,%6,%7}, {%8,%9}, {%0,%1,%2,%3};"
        : "+f"(c[0]), "+f"(c[1]), "+f"(c[2]), "+f"(c[3])
        : "r"(a0), "r"(a1), "r"(a2), "r"(a3), "r"(b0), "r"(b1));
}

// ---------------------------------------------------------------------------
// bf16 GEMM body: C(+bias) for one 128x128 tile at (m0, n0).
// mode: 0=f32, 1=+relu, 2=bf16 out, 3=bf16+relu.
// K-chunk 64, 3-stage cp.async pipeline, ldmatrix fragments, single barrier
// per chunk (issue into stage consumed at kc-1 right after the barrier).
// Stage: 128 rows x 144B per operand, A then B = 36864B; 3 stages = 110592B.
// ---------------------------------------------------------------------------
#define SSTR 36
#define STAGE_B (2 * 128 * SSTR * 4)  // 36864 bytes
#define BOFF_B (128 * SSTR * 4)      // 18432 bytes
#define NSTAGE 3

#define ISSUE(s, kc)                                                          \
    {                                                                         \
        const uint32_t so = sb + (uint32_t)(s) * STAGE_B;                     \
        _Pragma("unroll")                                                     \
        for (int i = 0; i < 4; i++) {                                         \
            const int r = r_ + (i << 5);                                      \
            const uint32_t off = ((uint32_t)(r * SSTR + (q_ << 2))) << 2;     \
            cp16(so + off, Abase + (size_t)r * rowstr + (size_t)(kc) * 8 + q_);\
            cp16(so + BOFF_B + off, Bbase + (size_t)r * rowstr + (size_t)(kc) * 8 + q_);\
        }                                                                     \
        asm volatile("cp.async.commit_group;" ::: "memory");                  \
    }

__device__ __forceinline__
void hgemm_body(const __nv_bfloat16* __restrict__ A, const __nv_bfloat16* __restrict__ Bt,
                const float* __restrict__ bias, void* __restrict__ Cv,
                int N, int K, int mode, int m0, int n0, uint32_t sb) {
    const int tid = threadIdx.x, wid = tid >> 5, lane = tid & 31;
    const int warp_m = (wid & 1) * 64;
    const int warp_n = (wid >> 1) * 32;
    const int lr = lane >> 2, lc = lane & 3;

    float c[4][4][4];
#pragma unroll
    for (int i = 0; i < 4; i++)
#pragma unroll
        for (int j = 0; j < 4; j++)
#pragma unroll
            for (int q = 0; q < 4; q++) c[i][j][q] = 0.f;

    const int nk = K >> 6;
    const int rowstr = K >> 3;   // 16B units per source row (bf16)
    const float4* Abase = (const float4*)(A + (size_t)m0 * K);
    const float4* Bbase = (const float4*)(Bt + (size_t)n0 * K);
    const int r_ = tid >> 3, q_ = tid & 7;

    const int quad = lane >> 3, rr = lane & 7;
    uint32_t aoff[4], boff[4];
#pragma unroll
    for (int i = 0; i < 4; i++)
        aoff[i] = (uint32_t)(((warp_m + (i << 4) + ((quad & 1) << 3) + rr) * SSTR
                              + ((quad >> 1) << 2)) << 2);
#pragma unroll
    for (int j = 0; j < 4; j++)
        boff[j] = (uint32_t)(((warp_n + (j << 3) + rr) * SSTR
                              + ((quad & 1) << 2)) << 2) + BOFF_B;

    ISSUE(0, 0);
    if (nk > 1) ISSUE(1, 1);
    int s = 0;
    for (int kc = 0; kc < nk; kc++) {
        if (kc + 1 < nk) {
            asm volatile("cp.async.wait_group 1;" ::: "memory");
        } else {
            asm volatile("cp.async.wait_group 0;" ::: "memory");
        }
        __syncthreads();
        if (kc + 2 < nk) {
            int sn = s + 2; if (sn >= NSTAGE) sn -= NSTAGE;
            ISSUE(sn, kc + 2);
        }

        const uint32_t sA = sb + (uint32_t)s * STAGE_B;
#pragma unroll
        for (int ks = 0; ks < 4; ks++) {
            const uint32_t k0b = (uint32_t)ks << 5;
            uint32_t af[4][4], bf[4][2];
#pragma unroll
            for (int i = 0; i < 4; i++)
                ldsm_x4(af[i][0], af[i][1], af[i][2], af[i][3], sA + aoff[i] + k0b);
#pragma unroll
            for (int j = 0; j < 4; j++)
                ldsm_x2(bf[j][0], bf[j][1], sA + boff[j] + k0b);
#pragma unroll
            for (int i = 0; i < 4; i++)
#pragma unroll
                for (int j = 0; j < 4; j++)
                    mma_bf16(c[i][j], af[i][0], af[i][1], af[i][2], af[i][3],
                             bf[j][0], bf[j][1]);
        }
        if (++s >= NSTAGE) s = 0;
    }

    // epilogue
#pragma unroll
    for (int i = 0; i < 4; i++) {
        const int r0 = m0 + warp_m + (i << 4) + lr;
#pragma unroll
        for (int j = 0; j < 4; j++) {
            const int c0 = n0 + warp_n + (j << 3) + (lc << 1);
            const float b0 = bias[c0], b1 = bias[c0 + 1];
            float v0 = c[i][j][0] + b0, v1 = c[i][j][1] + b1;
            float v2 = c[i][j][2] + b0, v3 = c[i][j][3] + b1;
            if (mode & 1) {
                v0 = fmaxf(v0, 0.f); v1 = fmaxf(v1, 0.f);
                v2 = fmaxf(v2, 0.f); v3 = fmaxf(v3, 0.f);
            }
            if (mode & 2) {
                __nv_bfloat16* Ch = (__nv_bfloat16*)Cv;
                __nv_bfloat162 p0, p1;
                p0.x = __float2bfloat16_rn(v0); p0.y = __float2bfloat16_rn(v1);
                p1.x = __float2bfloat16_rn(v2); p1.y = __float2bfloat16_rn(v3);
                *(__nv_bfloat162*)(Ch + (size_t)r0 * N + c0) = p0;
                *(__nv_bfloat162*)(Ch + (size_t)(r0 + 8) * N + c0) = p1;
            } else {
                float* C = (float*)Cv;
                *(float2*)(C + (size_t)r0 * N + c0) = make_float2(v0, v1);
                *(float2*)(C + (size_t)(r0 + 8) * N + c0) = make_float2(v2, v3);
            }
        }
    }
}

// generic GEMM kernel (outproj, FFN)
__global__ __launch_bounds__(256)
void hgemm(const __nv_bfloat16* __restrict__ A, const __nv_bfloat16* __restrict__ Bt,
           const float* __restrict__ bias, void* __restrict__ Cv,
           int M, int N, int K, int mode) {
    extern __shared__ float smem[];
    hgemm_body(A, Bt, bias, Cv, N, K, mode, blockIdx.y << 7, blockIdx.x << 7, s2u(smem));
}

// fused value-proj + offattn-proj (independent GEMMs, one launch to share the
// wave tail). grid = (5, 340): bx 0-1 = value proj (N=256, bf16 out),
// bx 2-4 = offsets+attn proj (N=384, f32 out).
__global__ __launch_bounds__(256)
void proj_kernel(const float* __restrict__ b_value) {
    extern __shared__ float smem[];
    const uint32_t sb = s2u(smem);
    const int m0 = blockIdx.y << 7;
    if (blockIdx.x < 2) {
        hgemm_body(g_srch, g_WvTh, b_value, g_valueh, 256, 256, 2,
                   m0, blockIdx.x << 7, sb);
    } else {
        hgemm_body(g_queryh, g_WoaTh, g_boa, g_oa, 384, 256, 0,
                   m0, (blockIdx.x - 2) << 7, sb);
    }
}

// ---------------------------------------------------------------------------
// prep: all weight transposes (f32 -> bf16 K-major) + bias concat, one kernel.
// ---------------------------------------------------------------------------
__device__ __forceinline__ void tr_tile_h(float t[32][33],
                                          const float* __restrict__ in,
                                          __nv_bfloat16* __restrict__ out,
                                          int C_in, int out_stride,
                                          int tx, int ty, int orow_off) {
    const int tyid = threadIdx.x >> 5, txid = threadIdx.x & 31;
    t[tyid][txid] = in[(size_t)(ty * 32 + tyid) * C_in + tx * 32 + txid];
    __syncthreads();
    out[(size_t)(orow_off + tx * 32 + tyid) * out_stride + ty * 32 + txid] =
        __float2bfloat16_rn(t[txid][tyid]);
}

__global__ __launch_bounds__(1024)
void prep_w(const float* __restrict__ Wv, const float* __restrict__ Woff,
            const float* __restrict__ Wattn, const float* __restrict__ Wout,
            const float* __restrict__ W1, const float* __restrict__ W2,
            const float* __restrict__ boff, const float* __restrict__ battn) {
    __shared__ float t[32][33];
    const int b = blockIdx.x;
    if (b < 64) {
        tr_tile_h(t, Wv, g_WvTh, 256, 256, b & 7, b >> 3, 0);
    } else if (b < 128) {
        const int l = b - 64;
        tr_tile_h(t, Woff, g_WoaTh, 256, 256, l & 7, l >> 3, 0);
    } else if (b < 160) {
        const int l = b - 128;
        tr_tile_h(t, Wattn, g_WoaTh, 128, 256, l & 3, l >> 2, 256);
    } else if (b < 224) {
        const int l = b - 160;
        tr_tile_h(t, Wout, g_WoutTh, 256, 256, l & 7, l >> 3, 0);
    } else if (b < 480) {
        const int l = b - 224;
        tr_tile_h(t, W1, g_W1Th, 1024, 256, l & 31, l >> 5, 0);
    } else if (b < 736) {
        const int l = b - 480;
        tr_tile_h(t, W2, g_W2Th, 256, 1024, l & 7, l >> 3, 0);
    } else {
        const int tid = threadIdx.x;
        if (tid < 256) g_boa[tid] = boff[tid];
        else if (tid < 384) g_boa[tid] = battn[tid - 256];
    }
}

// ---------------------------------------------------------------------------
// srch = bf16(src); queryh = bf16(src + pos)
// ---------------------------------------------------------------------------
__global__ void add2_kernel(const float4* __restrict__ src, const float4* __restrict__ pos,
                            __nv_bfloat16* __restrict__ srch,
                            __nv_bfloat16* __restrict__ queryh, int n4) {
    int i = blockIdx.x * blockDim.x + threadIdx.x;
    if (i < n4) {
        float4 s = src[i], p = pos[i];
        __nv_bfloat162 s0, s1, q0, q1;
        s0.x = __float2bfloat16_rn(s.x); s0.y = __float2bfloat16_rn(s.y);
        s1.x = __float2bfloat16_rn(s.z); s1.y = __float2bfloat16_rn(s.w);
        q0.x = __float2bfloat16_rn(s.x + p.x); q0.y = __float2bfloat16_rn(s.y + p.y);
        q1.x = __float2bfloat16_rn(s.z + p.z); q1.y = __float2bfloat16_rn(s.w + p.w);
        uint2 us, uq;
        us.x = *(uint32_t*)&s0; us.y = *(uint32_t*)&s1;
        uq.x = *(uint32_t*)&q0; uq.y = *(uint32_t*)&q1;
        *(uint2*)(srch + (size_t)i * 4) = us;
        *(uint2*)(queryh + (size_t)i * 4) = uq;
    }
}

// ---------------------------------------------------------------------------
// deformable attention sampling from bf16 value.
// 256 threads = 8 warps = 4 tokens/block. Each warp serves 4 heads:
// 8 lanes per head, each lane owns 4 consecutive bf16 channels (uint2 load).
// ---------------------------------------------------------------------------
__global__ __launch_bounds__(256)
void deform_kernel(const float* __restrict__ refp) {
    const int wid = threadIdx.x >> 5, lane = threadIdx.x & 31;
    const int gw = blockIdx.x * 8 + wid;
    const int m = gw >> 1;
    const int h = ((gw & 1) << 2) + (lane >> 3);
    const int g = lane & 7;
    const int b = m / LQ;

    const int lvlH[NLVL] = {64, 32, 16, 8};
    const int lvlW[NLVL] = {64, 32, 16, 8};
    const int lvlS[NLVL] = {0, 4096, 5120, 5376};

    const float* logit = g_oa + (size_t)m * 384 + 256 + h * 16;
    float mx = -1e30f;
#pragma unroll
    for (int i = 0; i < 16; i++) mx = fmaxf(mx, logit[i]);
    float w[16];
    float sum = 0.f;
#pragma unroll
    for (int i = 0; i < 16; i++) { w[i] = expf(logit[i] - mx); sum += w[i]; }
    const float inv = 1.f / sum;

    const float* off = g_oa + (size_t)m * 384 + h * 32;
    const float* rp = refp + (size_t)m * NLVL * 2;

    float acc0 = 0.f, acc1 = 0.f, acc2 = 0.f, acc3 = 0.f;
#pragma unroll
    for (int l = 0; l < NLVL; l++) {
        const int H = lvlH[l], W = lvlW[l], S = lvlS[l];
        const float rx = rp[l * 2 + 0];
        const float ry = rp[l * 2 + 1];
        const float invW = 1.f / (float)W;
        const float invH = 1.f / (float)H;
        const __nv_bfloat16* vb =
            g_valueh + ((size_t)b * LQ + S) * DIM + h * HDIM + (g << 2);
#pragma unroll
        for (int p = 0; p < NPT; p++) {
            const int oi = (l * NPT + p) * 2;
            const float lx = rx + off[oi + 0] * invW;
            const float ly = ry + off[oi + 1] * invH;
            const float x = lx * (float)W - 0.5f;
            const float y = ly * (float)H - 0.5f;
            const float x0f = floorf(x), y0f = floorf(y);
            const int x0 = (int)x0f, y0 = (int)y0f;
            const float wx1 = x - x0f, wy1 = y - y0f;
            const float wx0 = 1.f - wx1, wy0 = 1.f - wy1;

            const bool xin0 = (x0 >= 0) & (x0 < W);
            const bool xin1 = (x0 + 1 >= 0) & (x0 + 1 < W);
            const bool yin0 = (y0 >= 0) & (y0 < H);
            const bool yin1 = (y0 + 1 >= 0) & (y0 + 1 < H);

            uint2 u00 = make_uint2(0u, 0u), u01 = u00, u10 = u00, u11 = u00;
            if (yin0 & xin0) u00 = *(const uint2*)(vb + (size_t)(y0 * W + x0) * DIM);
            if (yin0 & xin1) u01 = *(const uint2*)(vb + (size_t)(y0 * W + x0 + 1) * DIM);
            if (yin1 & xin0) u10 = *(const uint2*)(vb + (size_t)((y0 + 1) * W + x0) * DIM);
            if (yin1 & xin1) u11 = *(const uint2*)(vb + (size_t)((y0 + 1) * W + x0 + 1) * DIM);

            const float wt = w[l * NPT + p] * inv;
            const float w00 = wt * wx0 * wy0, w01 = wt * wx1 * wy0;
            const float w10 = wt * wx0 * wy1, w11 = wt * wx1 * wy1;

            float2 a0 = __bfloat1622float2(*(__nv_bfloat162*)&u00.x);
            float2 a1 = __bfloat1622float2(*(__nv_bfloat162*)&u00.y);
            float2 b0 = __bfloat1622float2(*(__nv_bfloat162*)&u01.x);
            float2 b1 = __bfloat1622float2(*(__nv_bfloat162*)&u01.y);
            float2 c0 = __bfloat1622float2(*(__nv_bfloat162*)&u10.x);
            float2 c1 = __bfloat1622float2(*(__nv_bfloat162*)&u10.y);
            float2 d0 = __bfloat1622float2(*(__nv_bfloat162*)&u11.x);
            float2 d1 = __bfloat1622float2(*(__nv_bfloat162*)&u11.y);

            acc0 = fmaf(w00, a0.x, fmaf(w01, b0.x, fmaf(w10, c0.x, fmaf(w11, d0.x, acc0))));
            acc1 = fmaf(w00, a0.y, fmaf(w01, b0.y, fmaf(w10, c0.y, fmaf(w11, d0.y, acc1))));
            acc2 = fmaf(w00, a1.x, fmaf(w01, b1.x, fmaf(w10, c1.x, fmaf(w11, d1.x, acc2))));
            acc3 = fmaf(w00, a1.y, fmaf(w01, b1.y, fmaf(w10, c1.y, fmaf(w11, d1.y, acc3))));
        }
    }
    __nv_bfloat162 p0, p1;
    p0.x = __float2bfloat16_rn(acc0); p0.y = __float2bfloat16_rn(acc1);
    p1.x = __float2bfloat16_rn(acc2); p1.y = __float2bfloat16_rn(acc3);
    uint2 st;
    st.x = *(uint32_t*)&p0; st.y = *(uint32_t*)&p1;
    *(uint2*)(g_attnouth + (size_t)m * DIM + h * HDIM + (g << 2)) = st;
}

// ---------------------------------------------------------------------------
// fused residual + LayerNorm, warp-per-token (no smem, no block sync).
// 256 threads = 8 warps = 8 tokens/block; lane owns 8 channels (2x float4).
// ---------------------------------------------------------------------------
__global__ __launch_bounds__(256)
void ln_kernel(const float* __restrict__ a, const float* __restrict__ b,
               const float* __restrict__ gam, const float* __restrict__ bet,
               float* __restrict__ o, __nv_bfloat16* __restrict__ oh) {
    const int w = threadIdx.x >> 5, lane = threadIdx.x & 31;
    const int m = blockIdx.x * 8 + w;
    const size_t base = (size_t)m * DIM;
    const int c0 = lane << 2;          // cols c0..c0+3 and c0+128..c0+131

    float4 a0 = *(const float4*)(a + base + c0);
    float4 a1 = *(const float4*)(a + base + 128 + c0);
    float4 b0 = *(const float4*)(b + base + c0);
    float4 b1 = *(const float4*)(b + base + 128 + c0);

    float v[8] = {a0.x + b0.x, a0.y + b0.y, a0.z + b0.z, a0.w + b0.w,
                  a1.x + b1.x, a1.y + b1.y, a1.z + b1.z, a1.w + b1.w};

    float s = 0.f;
#pragma unroll
    for (int i = 0; i < 8; i++) s += v[i];
#pragma unroll
    for (int off = 16; off > 0; off >>= 1) s += __shfl_xor_sync(0xffffffffu, s, off);
    const float mu = s * (1.f / DIM);

    float d[8], sv = 0.f;
#pragma unroll
    for (int i = 0; i < 8; i++) { d[i] = v[i] - mu; sv += d[i] * d[i]; }
#pragma unroll
    for (int off = 16; off > 0; off >>= 1) sv += __shfl_xor_sync(0xffffffffu, sv, off);
    const float rs = rsqrtf(sv * (1.f / DIM) + 1e-5f);

    float4 g0 = *(const float4*)(gam + c0);
    float4 g1 = *(const float4*)(gam + 128 + c0);
    float4 be0 = *(const float4*)(bet + c0);
    float4 be1 = *(const float4*)(bet + 128 + c0);

    float r[8];
    r[0] = d[0] * rs * g0.x + be0.x; r[1] = d[1] * rs * g0.y + be0.y;
    r[2] = d[2] * rs * g0.z + be0.z; r[3] = d[3] * rs * g0.w + be0.w;
    r[4] = d[4] * rs * g1.x + be1.x; r[5] = d[5] * rs * g1.y + be1.y;
    r[6] = d[6] * rs * g1.z + be1.z; r[7] = d[7] * rs * g1.w + be1.w;

    *(float4*)(o + base + c0) = make_float4(r[0], r[1], r[2], r[3]);
    *(float4*)(o + base + 128 + c0) = make_float4(r[4], r[5], r[6], r[7]);
    if (oh) {
        __nv_bfloat162 h0, h1, h2, h3;
        h0.x = __float2bfloat16_rn(r[0]); h0.y = __float2bfloat16_rn(r[1]);
        h1.x = __float2bfloat16_rn(r[2]); h1.y = __float2bfloat16_rn(r[3]);
        h2.x = __float2bfloat16_rn(r[4]); h2.y = __float2bfloat16_rn(r[5]);
        h3.x = __float2bfloat16_rn(r[6]); h3.y = __float2bfloat16_rn(r[7]);
        uint2 u0, u1;
        u0.x = *(uint32_t*)&h0; u0.y = *(uint32_t*)&h1;
        u1.x = *(uint32_t*)&h2; u1.y = *(uint32_t*)&h3;
        *(uint2*)(oh + base + c0) = u0;
        *(uint2*)(oh + base + 128 + c0) = u1;
    }
}

// ---------------------------------------------------------------------------
extern "C" void kernel_launch(void* const* d_in, const int* in_sizes, int n_in,
                              void* d_out, int out_size) {
    const float* src    = (const float*)d_in[0];
    const float* pos    = (const float*)d_in[1];
    const float* refp   = (const float*)d_in[2];
    const float* W_value = (const float*)d_in[4];
    const float* b_value = (const float*)d_in[5];
    const float* W_off   = (const float*)d_in[6];
    const float* b_off   = (const float*)d_in[7];
    const float* W_attn  = (const float*)d_in[8];
    const float* b_attn  = (const float*)d_in[9];
    const float* W_out   = (const float*)d_in[10];
    const float* b_out   = (const float*)d_in[11];
    const float* ln1g    = (const float*)d_in[12];
    const float* ln1b    = (const float*)d_in[13];
    const float* W1      = (const float*)d_in[14];
    const float* b1      = (const float*)d_in[15];
    const float* W2      = (const float*)d_in[16];
    const float* b2      = (const float*)d_in[17];
    const float* ln2g    = (const float*)d_in[18];
    const float* ln2b    = (const float*)d_in[19];
    float* out = (float*)d_out;

    float *query, *ffnout, *x;
    __nv_bfloat16 *srch, *queryh, *attnouth, *xh, *hiddenh;
    __nv_bfloat16 *WoutTh, *W1Th, *W2Th;
    cudaGetSymbolAddress((void**)&query,    g_query);
    cudaGetSymbolAddress((void**)&srch,     g_srch);
    cudaGetSymbolAddress((void**)&queryh,   g_queryh);
    cudaGetSymbolAddress((void**)&attnouth, g_attnouth);
    cudaGetSymbolAddress((void**)&ffnout,   g_ffnout);
    cudaGetSymbolAddress((void**)&x,        g_x);
    cudaGetSymbolAddress((void**)&xh,       g_xh);
    cudaGetSymbolAddress((void**)&hiddenh,  g_hiddenh);
    cudaGetSymbolAddress((void**)&WoutTh, g_WoutTh);
    cudaGetSymbolAddress((void**)&W1Th,  g_W1Th);
    cudaGetSymbolAddress((void**)&W2Th,  g_W2Th);

    const int SMEM = NSTAGE * STAGE_B;   // 110592
    cudaFuncSetAttribute(hgemm, cudaFuncAttributeMaxDynamicSharedMemorySize, SMEM);
    cudaFuncSetAttribute(proj_kernel, cudaFuncAttributeMaxDynamicSharedMemorySize, SMEM);

    const int M = NTOK;
    const int n4 = NTOK * DIM / 4;

    // 1: weight prep (bf16 transposed)
    prep_w<<<737, 1024>>>(W_value, W_off, W_attn, W_out, W1, W2, b_off, b_attn);

    // 2: srch = bf16(src); queryh = bf16(src + pos)
    add2_kernel<<<(n4 + 255) / 256, 256>>>((const float4*)src, (const float4*)pos,
                                           srch, queryh, n4);

    // 3: fused value-proj + offattn-proj (one launch, shared wave tail)
    proj_kernel<<<dim3(5, M / 128), 256, SMEM>>>(b_value);

    // 4: deformable sampling + attention-weighted sum -> bf16
    deform_kernel<<<M / 4, 256>>>(refp);

    // 5: output projection -> src2 f32
    hgemm<<<dim3(2, M / 128), 256, SMEM>>>(attnouth, WoutTh, b_out, query, M, DIM, DIM, 0);

    // 6: x = LN(src + src2), also bf16 copy for FFN
    ln_kernel<<<M / 8, 256>>>(src, query, ln1g, ln1b, x, xh);

    // 7-8: FFN in bf16 (hidden bf16+relu; FFN2 f32 out)
    hgemm<<<dim3(8, M / 128), 256, SMEM>>>(xh,      W1Th, b1, hiddenh, M, DFFN, DIM, 3);
    hgemm<<<dim3(2, M / 128), 256, SMEM>>>(hiddenh, W2Th, b2, ffnout,  M, DIM, DFFN, 0);

    // 9: out = LN(x + ffn)
    ln_kernel<<<M / 8, 256>>>(x, ffnout, ln2g, ln2b, out, nullptr);
}